// round 1
// baseline (speedup 1.0000x reference)
#include <cuda_runtime.h>
#include <math.h>

// ---------------------------------------------------------------------------
// GAT (2 layers) on GB300.
// Strategy: build CSR-by-receiver each call (hist -> scan -> scatter), then
// warp-per-node softmax aggregation with zero atomics in the heavy phase.
// All node tables fit in L2 (126MB), so random sender-row gathers are L2 hits.
// ---------------------------------------------------------------------------

constexpr int N_NODES = 100000;
constexpr int N_EDGES = 1600000;
constexpr int IN_DIM  = 128;
constexpr int HEADS1  = 4;
constexpr int F1      = 16;     // hidden per head
constexpr int HIDDEN  = 64;     // HEADS1 * F1
constexpr int CLASSES = 16;
constexpr float NEG   = 0.2f;
constexpr float EPS_D = 1e-9f;

constexpr int NPART = (N_NODES + 255) / 256;   // 391 scan chunks

// Scratch (static device globals; no allocation allowed)
__device__ float g_h1[N_NODES * HIDDEN];      // layer-1 projected features [n][64]
__device__ float g_s1src[N_NODES * HEADS1];
__device__ float g_s1dst[N_NODES * HEADS1];
__device__ float g_h2[N_NODES * CLASSES];     // layer-2 projected features [n][16]
__device__ float g_s2src[N_NODES];
__device__ float g_s2dst[N_NODES];
__device__ int   g_deg[N_NODES];
__device__ int   g_off[N_NODES + 1];
__device__ int   g_cur[N_NODES];
__device__ int   g_part[NPART];
__device__ int   g_partscan[NPART];
__device__ int   g_srcsorted[N_EDGES];        // sender id, sorted by receiver

__device__ __forceinline__ float lrelu(float x) { return fmaxf(x, NEG * x); }
__device__ __forceinline__ float elu(float x)   { return x > 0.f ? x : expm1f(x); }

// ------------------------------ CSR build ----------------------------------

__global__ void zero_deg_kernel() {
    int i = blockIdx.x * blockDim.x + threadIdx.x;
    if (i < N_NODES) g_deg[i] = 0;
}

__global__ void hist_kernel(const int* __restrict__ rcv) {
    int i = blockIdx.x * blockDim.x + threadIdx.x;
    if (i < N_EDGES) atomicAdd(&g_deg[rcv[i]], 1);
}

__global__ void scan1_kernel() {
    __shared__ int s[256];
    int i = blockIdx.x * 256 + threadIdx.x;
    int v = (i < N_NODES) ? g_deg[i] : 0;
    s[threadIdx.x] = v;
    __syncthreads();
    for (int o = 128; o; o >>= 1) {
        if (threadIdx.x < o) s[threadIdx.x] += s[threadIdx.x + o];
        __syncthreads();
    }
    if (threadIdx.x == 0) g_part[blockIdx.x] = s[0];
}

__global__ void scan2_kernel() {
    __shared__ int s[512];
    int t = threadIdx.x;
    int mine = (t < NPART) ? g_part[t] : 0;
    s[t] = mine;
    __syncthreads();
    for (int o = 1; o < 512; o <<= 1) {
        int v = (t >= o) ? s[t - o] : 0;
        __syncthreads();
        s[t] += v;
        __syncthreads();
    }
    if (t < NPART) g_partscan[t] = s[t] - mine;   // exclusive
}

__global__ void scan3_kernel() {
    __shared__ int s[256];
    int t = threadIdx.x;
    int i = blockIdx.x * 256 + t;
    int mine = (i < N_NODES) ? g_deg[i] : 0;
    s[t] = mine;
    __syncthreads();
    for (int o = 1; o < 256; o <<= 1) {
        int v = (t >= o) ? s[t - o] : 0;
        __syncthreads();
        s[t] += v;
        __syncthreads();
    }
    int excl = s[t] - mine;
    int base = g_partscan[blockIdx.x];
    if (i < N_NODES) {
        g_off[i] = base + excl;
        g_cur[i] = base + excl;
    }
    if (i == 0) g_off[N_NODES] = N_EDGES;
}

__global__ void scatter_kernel(const int* __restrict__ snd, const int* __restrict__ rcv) {
    int i = blockIdx.x * blockDim.x + threadIdx.x;
    if (i < N_EDGES) {
        int p = atomicAdd(&g_cur[rcv[i]], 1);
        g_srcsorted[p] = snd[i];
    }
}

// ---------------------- Layer-1 projection (GEMM) --------------------------
// h1[n][64] = x[n][128] @ W1 (W staged in SMEM, 64 accumulators / thread),
// plus attention score vectors s1src/s1dst.

__global__ void __launch_bounds__(256) proj1_kernel(
    const float* __restrict__ x, const float* __restrict__ W1,
    const float* __restrict__ a1s_, const float* __restrict__ a1d_)
{
    __shared__ float Ws[IN_DIM * HIDDEN];   // [k][64], 32KB
    __shared__ float as[HIDDEN], ad[HIDDEN];
    int t = threadIdx.x;
    for (int i = t; i < HEADS1 * IN_DIM * F1; i += 256) {
        int h = i >> 11;           // / (128*16)
        int k = (i >> 4) & 127;
        int f = i & 15;
        Ws[k * HIDDEN + h * 16 + f] = W1[i];
    }
    if (t < HIDDEN) { as[t] = a1s_[t]; ad[t] = a1d_[t]; }
    __syncthreads();

    int node = blockIdx.x * 256 + t;
    if (node >= N_NODES) return;

    float acc[HIDDEN];
#pragma unroll
    for (int c = 0; c < HIDDEN; c++) acc[c] = 0.f;

    const float4* xr = (const float4*)(x + node * IN_DIM);
#pragma unroll 2
    for (int k4 = 0; k4 < IN_DIM / 4; k4++) {
        float4 xv = xr[k4];
#pragma unroll
        for (int kk = 0; kk < 4; kk++) {
            float xk = (kk == 0) ? xv.x : (kk == 1) ? xv.y : (kk == 2) ? xv.z : xv.w;
            const float4* wrow = (const float4*)&Ws[(k4 * 4 + kk) * HIDDEN];
#pragma unroll
            for (int c4 = 0; c4 < HIDDEN / 4; c4++) {
                float4 w = wrow[c4];
                acc[c4 * 4 + 0] = fmaf(xk, w.x, acc[c4 * 4 + 0]);
                acc[c4 * 4 + 1] = fmaf(xk, w.y, acc[c4 * 4 + 1]);
                acc[c4 * 4 + 2] = fmaf(xk, w.z, acc[c4 * 4 + 2]);
                acc[c4 * 4 + 3] = fmaf(xk, w.w, acc[c4 * 4 + 3]);
            }
        }
    }

    float4* h1r = (float4*)&g_h1[node * HIDDEN];
#pragma unroll
    for (int c4 = 0; c4 < HIDDEN / 4; c4++)
        h1r[c4] = make_float4(acc[c4 * 4], acc[c4 * 4 + 1], acc[c4 * 4 + 2], acc[c4 * 4 + 3]);

#pragma unroll
    for (int h = 0; h < HEADS1; h++) {
        float ss = 0.f, sd = 0.f;
#pragma unroll
        for (int f = 0; f < F1; f++) {
            ss = fmaf(acc[h * 16 + f], as[h * 16 + f], ss);
            sd = fmaf(acc[h * 16 + f], ad[h * 16 + f], sd);
        }
        g_s1src[node * HEADS1 + h] = ss;
        g_s1dst[node * HEADS1 + h] = sd;
    }
}

// -------------- Layer-1 aggregation + elu + layer-2 projection -------------
// One warp per node. Lane l owns output columns 2l, 2l+1 (one head each).
// Pass A: segment max per head. Pass B: alpha, denom, 64-wide accumulation
// with coalesced h1[sender] row reads. Epilogue: elu, 64->16 projection,
// layer-2 score vectors. Zero atomics.

__global__ void __launch_bounds__(256) agg1_kernel(
    const float* __restrict__ W2, const float* __restrict__ a2src,
    const float* __restrict__ a2dst)
{
    __shared__ float W2s[HIDDEN * CLASSES];   // 4KB
    __shared__ float a2ss[CLASSES], a2ds[CLASSES];
    __shared__ float alphas[8][128];          // per-warp: 32 edges x 4 heads
    __shared__ int   snds[8][32];

    int t = threadIdx.x;
    for (int i = t; i < HIDDEN * CLASSES; i += 256) W2s[i] = W2[i];
    if (t < CLASSES) { a2ss[t] = a2src[t]; a2ds[t] = a2dst[t]; }
    __syncthreads();

    int lane = t & 31, wl = t >> 5;
    int node = blockIdx.x * 8 + wl;
    if (node >= N_NODES) return;

    int off0 = g_off[node], off1 = g_off[node + 1];
    float4 sdst = *(const float4*)&g_s1dst[node * 4];

    // pass A: per-head max
    float4 em = make_float4(-1e30f, -1e30f, -1e30f, -1e30f);
    for (int b = off0; b < off1; b += 32) {
        int i = b + lane;
        if (i < off1) {
            int s = g_srcsorted[i];
            float4 ss = *(const float4*)&g_s1src[s * 4];
            em.x = fmaxf(em.x, lrelu(ss.x + sdst.x));
            em.y = fmaxf(em.y, lrelu(ss.y + sdst.y));
            em.z = fmaxf(em.z, lrelu(ss.z + sdst.z));
            em.w = fmaxf(em.w, lrelu(ss.w + sdst.w));
        }
    }
#pragma unroll
    for (int o = 16; o; o >>= 1) {
        em.x = fmaxf(em.x, __shfl_xor_sync(0xffffffffu, em.x, o));
        em.y = fmaxf(em.y, __shfl_xor_sync(0xffffffffu, em.y, o));
        em.z = fmaxf(em.z, __shfl_xor_sync(0xffffffffu, em.z, o));
        em.w = fmaxf(em.w, __shfl_xor_sync(0xffffffffu, em.w, o));
    }

    // pass B
    int hsel = lane >> 3;                       // head for my 2 columns
    float2 acc = make_float2(0.f, 0.f);
    float4 asum = make_float4(0.f, 0.f, 0.f, 0.f);
    for (int b = off0; b < off1; b += 32) {
        int i = b + lane;
        int cnt = min(32, off1 - b);
        float4 al = make_float4(0.f, 0.f, 0.f, 0.f);
        int s = 0;
        if (i < off1) {
            s = g_srcsorted[i];
            float4 ss = *(const float4*)&g_s1src[s * 4];
            al.x = __expf(lrelu(ss.x + sdst.x) - em.x);
            al.y = __expf(lrelu(ss.y + sdst.y) - em.y);
            al.z = __expf(lrelu(ss.z + sdst.z) - em.z);
            al.w = __expf(lrelu(ss.w + sdst.w) - em.w);
            asum.x += al.x; asum.y += al.y; asum.z += al.z; asum.w += al.w;
        }
        snds[wl][lane] = s;
        *(float4*)&alphas[wl][lane * 4] = al;
        __syncwarp();
        for (int j = 0; j < cnt; j++) {
            float a = alphas[wl][j * 4 + hsel];
            int sj = snds[wl][j];
            float2 hv = *(const float2*)&g_h1[sj * HIDDEN + lane * 2];
            acc.x = fmaf(a, hv.x, acc.x);
            acc.y = fmaf(a, hv.y, acc.y);
        }
        __syncwarp();
    }
#pragma unroll
    for (int o = 16; o; o >>= 1) {
        asum.x += __shfl_xor_sync(0xffffffffu, asum.x, o);
        asum.y += __shfl_xor_sync(0xffffffffu, asum.y, o);
        asum.z += __shfl_xor_sync(0xffffffffu, asum.z, o);
        asum.w += __shfl_xor_sync(0xffffffffu, asum.w, o);
    }
    float den = (hsel == 0) ? asum.x : (hsel == 1) ? asum.y : (hsel == 2) ? asum.z : asum.w;
    float inv = 1.0f / (den + EPS_D);
    float r0 = elu(acc.x * inv);
    float r1 = elu(acc.y * inv);

    // stage elu'd h row in smem (reuse alpha buffer), then project 64->16
    alphas[wl][lane * 2]     = r0;
    alphas[wl][lane * 2 + 1] = r1;
    __syncwarp();
    if (lane < CLASSES) {
        float tv = 0.f;
#pragma unroll
        for (int k = 0; k < HIDDEN; k++)
            tv = fmaf(alphas[wl][k], W2s[k * CLASSES + lane], tv);
        g_h2[node * CLASSES + lane] = tv;
        float ps = tv * a2ss[lane];
        float pd = tv * a2ds[lane];
#pragma unroll
        for (int o = 8; o; o >>= 1) {
            ps += __shfl_down_sync(0x0000ffffu, ps, o);
            pd += __shfl_down_sync(0x0000ffffu, pd, o);
        }
        if (lane == 0) { g_s2src[node] = ps; g_s2dst[node] = pd; }
    }
}

// ------------------------- Layer-2 aggregation -----------------------------
// One warp per node, single head, 16 output cols. Two edges per inner step
// (lanes 0-15 edge j, lanes 16-31 edge j+1).

__global__ void __launch_bounds__(256) agg2_kernel(float* __restrict__ out)
{
    __shared__ float alphas[8][32];
    __shared__ int   snds[8][32];
    int t = threadIdx.x, lane = t & 31, wl = t >> 5;
    int node = blockIdx.x * 8 + wl;
    if (node >= N_NODES) return;

    int off0 = g_off[node], off1 = g_off[node + 1];
    float sd = g_s2dst[node];

    float em = -1e30f;
    for (int b = off0; b < off1; b += 32) {
        int i = b + lane;
        if (i < off1) {
            float e = lrelu(g_s2src[g_srcsorted[i]] + sd);
            em = fmaxf(em, e);
        }
    }
#pragma unroll
    for (int o = 16; o; o >>= 1) em = fmaxf(em, __shfl_xor_sync(0xffffffffu, em, o));

    float acc = 0.f, asum = 0.f;
    int halfsel = lane >> 4;
    int fcol = lane & 15;
    for (int b = off0; b < off1; b += 32) {
        int i = b + lane;
        int cnt = min(32, off1 - b);
        float al = 0.f; int s = 0;
        if (i < off1) {
            s = g_srcsorted[i];
            float e = lrelu(g_s2src[s] + sd);
            al = __expf(e - em);
            asum += al;
        }
        snds[wl][lane] = s;
        alphas[wl][lane] = al;
        __syncwarp();
        for (int j = 0; j < cnt; j += 2) {
            int jj = j + halfsel;             // jj <= 31 always; alpha=0 beyond cnt
            float a = alphas[wl][jj];
            int sj = snds[wl][jj];
            acc = fmaf(a, g_h2[sj * CLASSES + fcol], acc);
        }
        __syncwarp();
    }
    acc += __shfl_xor_sync(0xffffffffu, acc, 16);
#pragma unroll
    for (int o = 16; o; o >>= 1) asum += __shfl_xor_sync(0xffffffffu, asum, o);
    if (lane < CLASSES) out[node * CLASSES + lane] = acc / (asum + EPS_D);
}

// ------------------------------- launch ------------------------------------

extern "C" void kernel_launch(void* const* d_in, const int* in_sizes, int n_in,
                              void* d_out, int out_size)
{
    const float* x   = (const float*)d_in[0];
    const int*   snd = (const int*)  d_in[1];
    const int*   rcv = (const int*)  d_in[2];
    const float* W1  = (const float*)d_in[3];
    const float* a1s = (const float*)d_in[4];
    const float* a1d = (const float*)d_in[5];
    const float* W2  = (const float*)d_in[6];
    const float* a2s = (const float*)d_in[7];
    const float* a2d = (const float*)d_in[8];
    float* out = (float*)d_out;

    const int nb_nodes = (N_NODES + 255) / 256;   // 391
    const int nb_edges = (N_EDGES + 255) / 256;   // 6250
    const int nb_warp8 = (N_NODES + 7) / 8;       // 12500

    zero_deg_kernel<<<nb_nodes, 256>>>();
    hist_kernel<<<nb_edges, 256>>>(rcv);
    scan1_kernel<<<NPART, 256>>>();
    scan2_kernel<<<1, 512>>>();
    scan3_kernel<<<NPART, 256>>>();
    scatter_kernel<<<nb_edges, 256>>>(snd, rcv);

    proj1_kernel<<<nb_nodes, 256>>>(x, W1, a1s, a1d);
    agg1_kernel<<<nb_warp8, 256>>>(W2, a2s, a2d);
    agg2_kernel<<<nb_warp8, 256>>>(out);
}